// round 4
// baseline (speedup 1.0000x reference)
#include <cuda_runtime.h>
#include <math.h>

#define SEQ_LEN 8192
#define HIDDEN  768
#define BATCH   8
#define NFFT    8192     // packed complex FFT size
#define MFFT    16384    // real FFT size

// ---------------- static scratch (allocation-free rule) ----------------
__device__ float2 g_tw[NFFT];                         // exp(-2*pi*i*k/16384)
__device__ float  g_k [SEQ_LEN * HIDDEN];             // filter (L, D)
__device__ float2 g_Kf[HIDDEN * (NFFT + 1)];          // rfft(k)/16384 per d
__device__ float  g_xT[BATCH * HIDDEN * SEQ_LEN];     // x transposed (B*D, L)
__device__ float  g_yT[BATCH * HIDDEN * SEQ_LEN];     // y transposed (B*D, L)

__device__ __forceinline__ float2 cmul(float2 a, float2 b) {
    return make_float2(a.x * b.x - a.y * b.y, a.x * b.y + a.y * b.x);
}

// ---------------- twiddle init ----------------
__global__ void twiddle_init() {
    int k = blockIdx.x * blockDim.x + threadIdx.x;
    if (k < NFFT) {
        double a = -2.0 * M_PI * (double)k / (double)MFFT;
        g_tw[k] = make_float2((float)cos(a), (float)sin(a));
    }
}

// ---------------- implicit filter MLP + modulation ----------------
// grid: 512 blocks x 16 seq positions, 256 threads
__global__ void filter_kernel(
    const float* __restrict__ w_in,  const float* __restrict__ b_in,  const float* __restrict__ freq_in,
    const float* __restrict__ w_h0,  const float* __restrict__ b_h0,  const float* __restrict__ freq_h0,
    const float* __restrict__ w_h1,  const float* __restrict__ b_h1,  const float* __restrict__ freq_h1,
    const float* __restrict__ w_out)
{
    __shared__ float hA[16][64];
    __shared__ float hB[16][64];
    int l0 = blockIdx.x * 16;
    int tid = threadIdx.x;

    // input layer: z = [t, cos(phase), -sin(phase)], bands=1, f=1e-4
    for (int idx = tid; idx < 16 * 64; idx += 256) {
        int ll = idx >> 6, j = idx & 63;
        int l = l0 + ll;
        float t0 = (float)l / (float)(SEQ_LEN - 1);
        float ang = (float)(2.0 * M_PI * 1e-4 / (double)SEQ_LEN) * (float)l;
        float z1 = cosf(ang), z2 = -sinf(ang);
        float v = t0 * w_in[j] + z1 * w_in[64 + j] + z2 * w_in[128 + j] + b_in[j];
        hA[ll][j] = sinf(freq_in[j] * v);
    }
    __syncthreads();
    for (int idx = tid; idx < 16 * 64; idx += 256) {
        int ll = idx >> 6, j = idx & 63;
        float acc = b_h0[j];
#pragma unroll
        for (int i = 0; i < 64; i++) acc += hA[ll][i] * w_h0[i * 64 + j];
        hB[ll][j] = sinf(freq_h0[j] * acc);
    }
    __syncthreads();
    for (int idx = tid; idx < 16 * 64; idx += 256) {
        int ll = idx >> 6, j = idx & 63;
        float acc = b_h1[j];
#pragma unroll
        for (int i = 0; i < 64; i++) acc += hB[ll][i] * w_h1[i * 64 + j];
        hA[ll][j] = sinf(freq_h1[j] * acc);
    }
    __syncthreads();

    // output projection + exponential modulation (SHIFT = 0)
    const float MIND = 3.0701134573253943f;   // |log(0.01)/1.5|
    const float MAXD = 15.350567286626972f;   // |log(0.01)/0.3|
    for (int ll = 0; ll < 16; ll++) {
        int l = l0 + ll;
        float t0 = (float)l / (float)(SEQ_LEN - 1);
        for (int d = tid; d < HIDDEN; d += 256) {
            float acc = 0.f;
#pragma unroll
            for (int i = 0; i < 64; i++) acc += hA[ll][i] * w_out[i * HIDDEN + d];
            float ad = MIND + (MAXD - MIND) * ((float)d / 767.0f);
            g_k[(size_t)l * HIDDEN + d] = acc * expf(-t0 * ad);
        }
    }
}

// ---------------- transposes ----------------
__global__ void transpose_in(const float* __restrict__ x) {
    __shared__ float tile[32][33];
    int b = blockIdx.z;
    int l0 = blockIdx.x * 32, d0 = blockIdx.y * 32;
    int tx = threadIdx.x, ty = threadIdx.y; // (32, 8)
    const float* xb = x + (size_t)b * SEQ_LEN * HIDDEN;
#pragma unroll
    for (int r = 0; r < 4; r++)
        tile[ty + r * 8][tx] = xb[(size_t)(l0 + ty + r * 8) * HIDDEN + d0 + tx];
    __syncthreads();
#pragma unroll
    for (int r = 0; r < 4; r++)
        g_xT[(size_t)(b * HIDDEN + d0 + ty + r * 8) * SEQ_LEN + l0 + tx] = tile[tx][ty + r * 8];
}

__global__ void transpose_out(float* __restrict__ out) {
    __shared__ float tile[32][33];
    int b = blockIdx.z;
    int l0 = blockIdx.x * 32, d0 = blockIdx.y * 32;
    int tx = threadIdx.x, ty = threadIdx.y;
#pragma unroll
    for (int r = 0; r < 4; r++)
        tile[ty + r * 8][tx] = g_yT[(size_t)(b * HIDDEN + d0 + ty + r * 8) * SEQ_LEN + l0 + tx];
    __syncthreads();
    float* ob = out + (size_t)b * SEQ_LEN * HIDDEN;
#pragma unroll
    for (int r = 0; r < 4; r++)
        ob[(size_t)(l0 + ty + r * 8) * HIDDEN + d0 + tx] = tile[tx][ty + r * 8];
}

// ---------------- in-smem FFT (radix-2, 512 threads) ----------------
// DIF: natural order in -> bit-reversed out
__device__ void fft8192_dif(float2* S, int tid) {
    for (int s = 0; s < 13; s++) {
        int half = 4096 >> s;
        __syncthreads();
        for (int t = tid; t < 4096; t += 512) {
            int j  = t & (half - 1);
            int i0 = ((t >> (12 - s)) << (13 - s)) + j;
            int i1 = i0 + half;
            float2 u = S[i0], v = S[i1];
            float2 w = g_tw[j << (s + 1)];       // exp(-2pi i j / (8192>>s))
            S[i0] = make_float2(u.x + v.x, u.y + v.y);
            float2 dd = make_float2(u.x - v.x, u.y - v.y);
            S[i1] = cmul(dd, w);
        }
    }
    __syncthreads();
}

// DIT inverse (unnormalized): bit-reversed in -> natural out
__device__ void ifft8192_dit(float2* S, int tid) {
    for (int s = 0; s < 13; s++) {
        int half = 1 << s;
        __syncthreads();
        for (int t = tid; t < 4096; t += 512) {
            int j  = t & (half - 1);
            int i0 = ((t >> s) << (s + 1)) + j;
            int i1 = i0 + half;
            float2 w = g_tw[j << (13 - s)];      // conj applied below -> e^{+2pi i j/m}
            float2 u = S[i0], v = S[i1];
            float2 tv = make_float2(v.x * w.x + v.y * w.y, v.y * w.x - v.x * w.y);
            S[i0] = make_float2(u.x + tv.x, u.y + tv.y);
            S[i1] = make_float2(u.x - tv.x, u.y - tv.y);
        }
    }
    __syncthreads();
}

// ---------------- kernel spectrum: Kf[d][k] = rfft(pad(k[:,d]))/16384 ----------------
__global__ void __launch_bounds__(512) kf_kernel() {
    extern __shared__ float2 S[];
    int d = blockIdx.x;
    int tid = threadIdx.x;
    for (int n = tid; n < 4096; n += 512)
        S[n] = make_float2(g_k[(size_t)(2 * n) * HIDDEN + d],
                           g_k[(size_t)(2 * n + 1) * HIDDEN + d]);
    for (int n = 4096 + tid; n < 8192; n += 512)
        S[n] = make_float2(0.f, 0.f);
    fft8192_dif(S, tid);

    const float invM = 1.0f / 16384.0f;
    float2* Kf = g_Kf + (size_t)d * (NFFT + 1);
    if (tid == 0) {
        float2 c0 = S[0];
        Kf[0]    = make_float2((c0.x + c0.y) * invM, 0.f);   // U[0] real
        Kf[NFFT] = make_float2((c0.x - c0.y) * invM, 0.f);   // U[N] real
    }
    for (int t = tid; t < 4096; t += 512) {
        int k  = t + 1;
        int p1 = __brev(k) >> 19;
        int p2 = __brev(8192 - k) >> 19;
        float2 C1 = S[p1], C2 = S[p2];
        // E = (C1 + conj(C2))/2 ; O = -i*(C1 - conj(C2))/2
        float Ex = 0.5f * (C1.x + C2.x), Ey = 0.5f * (C1.y - C2.y);
        float Dx = C1.x - C2.x,          Dy = C1.y + C2.y;
        float Ox = 0.5f * Dy,            Oy = -0.5f * Dx;
        float2 w = g_tw[k];
        float wOx = Ox * w.x - Oy * w.y, wOy = Ox * w.y + Oy * w.x;
        Kf[k]        = make_float2((Ex + wOx) * invM, (Ey + wOy) * invM);   // U[k]
        Kf[8192 - k] = make_float2((Ex - wOx) * invM, -(Ey - wOy) * invM);  // conj(U[k+N]) = U[N-k]
    }
}

// ---------------- fused conv: load -> FFT -> pointwise -> iFFT -> +bias -> store ----------------
__global__ void __launch_bounds__(512) conv_kernel(const float* __restrict__ bias) {
    extern __shared__ float2 S[];
    int col = blockIdx.x;           // b*768 + d
    int d   = col % HIDDEN;
    int tid = threadIdx.x;

    const float2* row = (const float2*)(g_xT + (size_t)col * SEQ_LEN);
    for (int n = tid; n < 4096; n += 512) S[n] = row[n];
    for (int n = 4096 + tid; n < 8192; n += 512) S[n] = make_float2(0.f, 0.f);

    fft8192_dif(S, tid);

    const float2* Kf = g_Kf + (size_t)d * (NFFT + 1);
    if (tid == 0) {   // k = 0 bin (pairs with k = N): all real U's
        float2 c0 = S[0];
        float U0 = c0.x + c0.y, UN = c0.x - c0.y;
        float2 F0 = Kf[0], FN = Kf[NFFT];
        float2 Y0 = make_float2(U0 * F0.x, U0 * F0.y);
        float2 YN = make_float2(UN * FN.x, UN * FN.y);
        float Eyx = 0.5f * (Y0.x + YN.x), Eyy = 0.5f * (Y0.y + YN.y);
        float Dyx = 0.5f * (Y0.x - YN.x), Dyy = 0.5f * (Y0.y - YN.y);
        S[0] = make_float2(Eyx - Dyy, Eyy + Dyx);   // Z0 = Ey + i*Dy  (w=1)
    }
    for (int t = tid; t < 4096; t += 512) {
        int k  = t + 1;
        int k2 = 8192 - k;
        int p1 = __brev(k)  >> 19;
        int p2 = __brev(k2) >> 19;
        float2 C1 = S[p1], C2 = S[p2];
        // unpack: U[k] = E + w*O, U[k+N] = E - w*O
        float Ex = 0.5f * (C1.x + C2.x), Ey = 0.5f * (C1.y - C2.y);
        float Dx = C1.x - C2.x,          Dy = C1.y + C2.y;
        float Ox = 0.5f * Dy,            Oy = -0.5f * Dx;
        float2 w = g_tw[k];
        float wOx = Ox * w.x - Oy * w.y, wOy = Ox * w.y + Oy * w.x;
        float2 Uk  = make_float2(Ex + wOx, Ey + wOy);
        float2 UkN = make_float2(Ex - wOx, Ey - wOy);
        float2 F1 = Kf[k];
        float2 F2 = Kf[k2];
        // Y[k] = U[k]*Kf[k]; Y[k+N] = U[k+N]*conj(Kf[N-k])
        float2 Y1 = cmul(Uk, F1);
        float2 Y2 = cmul(UkN, make_float2(F2.x, -F2.y));
        // repack: Z[k] = (Y1+Y2)/2 + i*conj(w)*(Y1-Y2)/2
        float2 Eyc = make_float2(0.5f * (Y1.x + Y2.x), 0.5f * (Y1.y + Y2.y));
        float2 Dyc = make_float2(0.5f * (Y1.x - Y2.x), 0.5f * (Y1.y - Y2.y));
        float2 Oyc = make_float2(Dyc.x * w.x + Dyc.y * w.y, Dyc.y * w.x - Dyc.x * w.y);
        float2 Zk  = make_float2(Eyc.x - Oyc.y, Eyc.y + Oyc.x);
        // mirror bin k2 = N-k: U[N-k] = conj(U[k+N]); U[M-k] = conj(U[k])
        float2 Y1p = cmul(make_float2(UkN.x, -UkN.y), F2);
        float2 Y2p = cmul(make_float2(Uk.x, -Uk.y), make_float2(F1.x, -F1.y));
        float2 w2  = g_tw[k2];
        float2 Eyp = make_float2(0.5f * (Y1p.x + Y2p.x), 0.5f * (Y1p.y + Y2p.y));
        float2 Dyp = make_float2(0.5f * (Y1p.x - Y2p.x), 0.5f * (Y1p.y - Y2p.y));
        float2 Oyp = make_float2(Dyp.x * w2.x + Dyp.y * w2.y, Dyp.y * w2.x - Dyp.x * w2.y);
        float2 Zk2 = make_float2(Eyp.x - Oyp.y, Eyp.y + Oyp.x);
        S[p1] = Zk;
        S[p2] = Zk2;
    }

    ifft8192_dit(S, tid);

    const float invN = 1.0f / 8192.0f;
    float bv = bias[d];
    float2* orow = (float2*)(g_yT + (size_t)col * SEQ_LEN);
    for (int n = tid; n < 4096; n += 512)
        orow[n] = make_float2(S[n].x * invN + bv, S[n].y * invN + bv);
}

// ---------------- launch ----------------
extern "C" void kernel_launch(void* const* d_in, const int* in_sizes, int n_in,
                              void* d_out, int out_size) {
    const float* x       = (const float*)d_in[0];
    const float* w_in    = (const float*)d_in[1];
    const float* b_in    = (const float*)d_in[2];
    const float* freq_in = (const float*)d_in[3];
    const float* w_h0    = (const float*)d_in[4];
    const float* b_h0    = (const float*)d_in[5];
    const float* freq_h0 = (const float*)d_in[6];
    const float* w_h1    = (const float*)d_in[7];
    const float* b_h1    = (const float*)d_in[8];
    const float* freq_h1 = (const float*)d_in[9];
    const float* w_out   = (const float*)d_in[10];
    const float* bias    = (const float*)d_in[11];
    float* out = (float*)d_out;

    cudaFuncSetAttribute(kf_kernel,   cudaFuncAttributeMaxDynamicSharedMemorySize, 65536);
    cudaFuncSetAttribute(conv_kernel, cudaFuncAttributeMaxDynamicSharedMemorySize, 65536);

    twiddle_init<<<16, 512>>>();
    filter_kernel<<<SEQ_LEN / 16, 256>>>(w_in, b_in, freq_in, w_h0, b_h0, freq_h0,
                                         w_h1, b_h1, freq_h1, w_out);
    dim3 tgrid(SEQ_LEN / 32, HIDDEN / 32, BATCH);
    dim3 tblk(32, 8);
    transpose_in<<<tgrid, tblk>>>(x);
    kf_kernel<<<HIDDEN, 512, 65536>>>();
    conv_kernel<<<BATCH * HIDDEN, 512, 65536>>>(bias);
    transpose_out<<<tgrid, tblk>>>(out);
}

// round 5
// speedup vs baseline: 2.9837x; 2.9837x over previous
#include <cuda_runtime.h>
#include <math.h>

#define SEQ_LEN 8192
#define HIDDEN  768
#define BATCH   8
#define NFFT    8192     // packed complex FFT size
#define MFFT    16384    // real FFT size
#define SROW    18       // padded row stride (float2) for 16-element rows
#define SMEM_BYTES (512 * SROW * 8)   // 73728

// ---------------- static scratch (allocation-free rule) ----------------
__device__ float2 g_tw[NFFT];                         // exp(-2*pi*i*k/16384)
__device__ float  g_k [SEQ_LEN * HIDDEN];             // filter (L, D)
__device__ float  g_kT[HIDDEN * SEQ_LEN];             // filter transposed (D, L)
__device__ float2 g_Kf[HIDDEN * (NFFT + 1)];          // rfft(k)/16384 per d
__device__ float  g_xT[BATCH * HIDDEN * SEQ_LEN];     // x transposed (B*D, L)
__device__ float  g_yT[BATCH * HIDDEN * SEQ_LEN];     // y transposed (B*D, L)

__device__ __forceinline__ float2 cmul(float2 a, float2 b) {
    return make_float2(a.x * b.x - a.y * b.y, a.x * b.y + a.y * b.x);
}
__device__ __forceinline__ float2 cmulc(float2 a, float2 b) {   // a * conj(b)
    return make_float2(a.x * b.x + a.y * b.y, a.y * b.x - a.x * b.y);
}
__device__ __forceinline__ float2 csq(float2 a) {
    return make_float2(a.x * a.x - a.y * a.y, 2.0f * a.x * a.y);
}
__device__ __forceinline__ float2 mulni(float2 a) {  // a * (-i)
    return make_float2(a.y, -a.x);
}
__device__ __forceinline__ int PHYS(int i) { return ((i >> 4) * SROW) + (i & 15); }

// forward butterfly: a=u+v, b=(u-v)*w
#define FBF(a, b, w) { float2 u_=(a), v_=(b); (a)=make_float2(u_.x+v_.x,u_.y+v_.y); \
                       float2 d_=make_float2(u_.x-v_.x,u_.y-v_.y); (b)=cmul(d_, (w)); }
#define FBF1(a, b)   { float2 u_=(a), v_=(b); (a)=make_float2(u_.x+v_.x,u_.y+v_.y); \
                       (b)=make_float2(u_.x-v_.x,u_.y-v_.y); }
#define FBFNI(a, b)  { float2 u_=(a), v_=(b); (a)=make_float2(u_.x+v_.x,u_.y+v_.y); \
                       (b)=make_float2(u_.y-v_.y, -(u_.x-v_.x)); }
// inverse butterfly with FORWARD twiddle w (conj applied internally)
#define IBF(a, b, w) { float2 u_=(a); float2 tv_=cmulc((b),(w)); \
                       (a)=make_float2(u_.x+tv_.x,u_.y+tv_.y); (b)=make_float2(u_.x-tv_.x,u_.y-tv_.y); }
#define IBF1(a, b)   FBF1(a, b)
#define IBFPI(a, b)  { float2 u_=(a), v_=(b); float2 tv_=make_float2(-v_.y, v_.x); \
                       (a)=make_float2(u_.x+tv_.x,u_.y+tv_.y); (b)=make_float2(u_.x-tv_.x,u_.y-tv_.y); }

#define C8f 0.70710678118654752f
#define CAf 0.92387953251128676f
#define CBf 0.38268343236508977f

// ---------------- twiddle init ----------------
__global__ void twiddle_init() {
    int k = blockIdx.x * blockDim.x + threadIdx.x;
    if (k < NFFT) {
        double a = -2.0 * M_PI * (double)k / (double)MFFT;
        g_tw[k] = make_float2((float)cos(a), (float)sin(a));
    }
}

// ---------------- grouped forward stages s, s+1, s+2 (s in {0,3,6}) ----------------
template<int s>
__device__ __forceinline__ void fwd_group3(float2* S, int tid) {
    const int h = 1 << (10 - s);
#pragma unroll
    for (int it = 0; it < 2; it++) {
        int t = tid + it * 512;
        int r = t & (h - 1);
        int base = ((t >> (10 - s)) << (13 - s)) | r;
        float2 x[8];
#pragma unroll
        for (int e = 0; e < 8; e++) x[e] = S[PHYS(base + e * h)];
        float2 w1 = g_tw[r << (s + 1)];
        float2 w2 = csq(w1);
        float2 w4 = csq(w2);
        // stage s: pairs (e, e+4), w = w1 * exp(-i*pi*e/4)
        {
            float2 wr1 = cmul(w1, make_float2(C8f, -C8f));
            float2 wr2 = mulni(w1);
            float2 wr3 = cmul(w1, make_float2(-C8f, -C8f));
            FBF(x[0], x[4], w1);
            FBF(x[1], x[5], wr1);
            FBF(x[2], x[6], wr2);
            FBF(x[3], x[7], wr3);
        }
        // stage s+1: pairs (g+e, g+e+2), w = w2 * exp(-i*pi*e/2)
        {
            float2 w2n = mulni(w2);
            FBF(x[0], x[2], w2);
            FBF(x[1], x[3], w2n);
            FBF(x[4], x[6], w2);
            FBF(x[5], x[7], w2n);
        }
        // stage s+2: pairs (g, g+1), w = w4
        FBF(x[0], x[1], w4);
        FBF(x[2], x[3], w4);
        FBF(x[4], x[5], w4);
        FBF(x[6], x[7], w4);
#pragma unroll
        for (int e = 0; e < 8; e++) S[PHYS(base + e * h)] = x[e];
    }
}

// ---------------- forward stages 9..12 on 16 consecutive elements ----------------
__device__ __forceinline__ void fwd_group16(float2* S, int tid) {
    float2* row = S + tid * SROW;
    float2 x[16];
#pragma unroll
    for (int e = 0; e < 16; e++) x[e] = row[e];
    // stage 9: (e, e+8), w = exp(-i*pi*e/8)
    FBF1 (x[0], x[8]);
    FBF  (x[1], x[9],  make_float2( CAf, -CBf));
    FBF  (x[2], x[10], make_float2( C8f, -C8f));
    FBF  (x[3], x[11], make_float2( CBf, -CAf));
    FBFNI(x[4], x[12]);
    FBF  (x[5], x[13], make_float2(-CBf, -CAf));
    FBF  (x[6], x[14], make_float2(-C8f, -C8f));
    FBF  (x[7], x[15], make_float2(-CAf, -CBf));
    // stage 10: (g+e, g+e+4), w = exp(-i*pi*e/4)
#pragma unroll
    for (int g = 0; g < 16; g += 8) {
        FBF1 (x[g+0], x[g+4]);
        FBF  (x[g+1], x[g+5], make_float2( C8f, -C8f));
        FBFNI(x[g+2], x[g+6]);
        FBF  (x[g+3], x[g+7], make_float2(-C8f, -C8f));
    }
    // stage 11: (g+e, g+e+2), w = {1, -i}
#pragma unroll
    for (int g = 0; g < 16; g += 4) {
        FBF1 (x[g+0], x[g+2]);
        FBFNI(x[g+1], x[g+3]);
    }
    // stage 12: (g, g+1), w = 1
#pragma unroll
    for (int g = 0; g < 16; g += 2) FBF1(x[g], x[g+1]);
#pragma unroll
    for (int e = 0; e < 16; e++) row[e] = x[e];
}

// ---------------- inverse stages 0..3 on 16 consecutive elements ----------------
__device__ __forceinline__ void inv_group16(float2* S, int tid) {
    float2* row = S + tid * SROW;
    float2 x[16];
#pragma unroll
    for (int e = 0; e < 16; e++) x[e] = row[e];
    // stage 0: (g, g+1), w = 1
#pragma unroll
    for (int g = 0; g < 16; g += 2) IBF1(x[g], x[g+1]);
    // stage 1: (g+e, g+e+2), conj-tw = {1, +i}
#pragma unroll
    for (int g = 0; g < 16; g += 4) {
        IBF1 (x[g+0], x[g+2]);
        IBFPI(x[g+1], x[g+3]);
    }
    // stage 2: (g+e, g+e+4), fwd w = exp(-i*pi*e/4)
#pragma unroll
    for (int g = 0; g < 16; g += 8) {
        IBF1 (x[g+0], x[g+4]);
        IBF  (x[g+1], x[g+5], make_float2( C8f, -C8f));
        IBFPI(x[g+2], x[g+6]);
        IBF  (x[g+3], x[g+7], make_float2(-C8f, -C8f));
    }
    // stage 3: (e, e+8), fwd w = exp(-i*pi*e/8)
    IBF1 (x[0], x[8]);
    IBF  (x[1], x[9],  make_float2( CAf, -CBf));
    IBF  (x[2], x[10], make_float2( C8f, -C8f));
    IBF  (x[3], x[11], make_float2( CBf, -CAf));
    IBFPI(x[4], x[12]);
    IBF  (x[5], x[13], make_float2(-CBf, -CAf));
    IBF  (x[6], x[14], make_float2(-C8f, -C8f));
    IBF  (x[7], x[15], make_float2(-CAf, -CBf));
#pragma unroll
    for (int e = 0; e < 16; e++) row[e] = x[e];
}

// ---------------- grouped inverse stages s0, s0+1, s0+2 (s0 in {4,7,10}) -------
template<int s0>
__device__ __forceinline__ void inv_group3(float2* S, int tid) {
    const int h = 1 << s0;
#pragma unroll
    for (int it = 0; it < 2; it++) {
        int t = tid + it * 512;
        int r = t & (h - 1);
        int base = ((t >> s0) << (s0 + 3)) | r;
        float2 x[8];
#pragma unroll
        for (int e = 0; e < 8; e++) x[e] = S[PHYS(base + e * h)];
        float2 wB = g_tw[r << (11 - s0)];
        float2 wB2 = csq(wB);
        float2 wB4 = csq(wB2);
        // stage s0: pairs (g, g+1), fwd w = wB4
        IBF(x[0], x[1], wB4);
        IBF(x[2], x[3], wB4);
        IBF(x[4], x[5], wB4);
        IBF(x[6], x[7], wB4);
        // stage s0+1: pairs (g+e, g+e+2), fwd w = wB2 * exp(-i*pi*e/2)
        {
            float2 w2n = mulni(wB2);
            IBF(x[0], x[2], wB2);
            IBF(x[1], x[3], w2n);
            IBF(x[4], x[6], wB2);
            IBF(x[5], x[7], w2n);
        }
        // stage s0+2: pairs (e, e+4), fwd w = wB * exp(-i*pi*e/4)
        {
            float2 wr1 = cmul(wB, make_float2(C8f, -C8f));
            float2 wr2 = mulni(wB);
            float2 wr3 = cmul(wB, make_float2(-C8f, -C8f));
            IBF(x[0], x[4], wB);
            IBF(x[1], x[5], wr1);
            IBF(x[2], x[6], wr2);
            IBF(x[3], x[7], wr3);
        }
#pragma unroll
        for (int e = 0; e < 8; e++) S[PHYS(base + e * h)] = x[e];
    }
}

__device__ __forceinline__ void fft_fwd(float2* S, int tid) {
    fwd_group3<0>(S, tid); __syncthreads();
    fwd_group3<3>(S, tid); __syncthreads();
    fwd_group3<6>(S, tid); __syncthreads();
    fwd_group16(S, tid);   __syncthreads();
}
__device__ __forceinline__ void fft_inv(float2* S, int tid) {
    inv_group16(S, tid);   __syncthreads();
    inv_group3<4>(S, tid); __syncthreads();
    inv_group3<7>(S, tid); __syncthreads();
    inv_group3<10>(S, tid); __syncthreads();
}

// ---------------- implicit filter MLP + modulation ----------------
__global__ void filter_kernel(
    const float* __restrict__ w_in,  const float* __restrict__ b_in,  const float* __restrict__ freq_in,
    const float* __restrict__ w_h0,  const float* __restrict__ b_h0,  const float* __restrict__ freq_h0,
    const float* __restrict__ w_h1,  const float* __restrict__ b_h1,  const float* __restrict__ freq_h1,
    const float* __restrict__ w_out)
{
    __shared__ float hA[16][64];
    __shared__ float hB[16][64];
    int l0 = blockIdx.x * 16;
    int tid = threadIdx.x;

    for (int idx = tid; idx < 16 * 64; idx += 256) {
        int ll = idx >> 6, j = idx & 63;
        int l = l0 + ll;
        float t0 = (float)l / (float)(SEQ_LEN - 1);
        float ang = (float)(2.0 * M_PI * 1e-4 / (double)SEQ_LEN) * (float)l;
        float z1 = cosf(ang), z2 = -sinf(ang);
        float v = t0 * w_in[j] + z1 * w_in[64 + j] + z2 * w_in[128 + j] + b_in[j];
        hA[ll][j] = sinf(freq_in[j] * v);
    }
    __syncthreads();
    for (int idx = tid; idx < 16 * 64; idx += 256) {
        int ll = idx >> 6, j = idx & 63;
        float acc = b_h0[j];
#pragma unroll
        for (int i = 0; i < 64; i++) acc += hA[ll][i] * w_h0[i * 64 + j];
        hB[ll][j] = sinf(freq_h0[j] * acc);
    }
    __syncthreads();
    for (int idx = tid; idx < 16 * 64; idx += 256) {
        int ll = idx >> 6, j = idx & 63;
        float acc = b_h1[j];
#pragma unroll
        for (int i = 0; i < 64; i++) acc += hB[ll][i] * w_h1[i * 64 + j];
        hA[ll][j] = sinf(freq_h1[j] * acc);
    }
    __syncthreads();

    const float MIND = 3.0701134573253943f;
    const float MAXD = 15.350567286626972f;
    for (int ll = 0; ll < 16; ll++) {
        int l = l0 + ll;
        float t0 = (float)l / (float)(SEQ_LEN - 1);
        for (int d = tid; d < HIDDEN; d += 256) {
            float acc = 0.f;
#pragma unroll
            for (int i = 0; i < 64; i++) acc += hA[ll][i] * w_out[i * HIDDEN + d];
            float ad = MIND + (MAXD - MIND) * ((float)d / 767.0f);
            g_k[(size_t)l * HIDDEN + d] = acc * expf(-t0 * ad);
        }
    }
}

// ---------------- transposes ----------------
__global__ void transpose_in(const float* __restrict__ x) {
    __shared__ float tile[32][33];
    int b = blockIdx.z;
    int l0 = blockIdx.x * 32, d0 = blockIdx.y * 32;
    int tx = threadIdx.x, ty = threadIdx.y; // (32, 8)
    const float* xb = x + (size_t)b * SEQ_LEN * HIDDEN;
#pragma unroll
    for (int r = 0; r < 4; r++)
        tile[ty + r * 8][tx] = xb[(size_t)(l0 + ty + r * 8) * HIDDEN + d0 + tx];
    __syncthreads();
#pragma unroll
    for (int r = 0; r < 4; r++)
        g_xT[(size_t)(b * HIDDEN + d0 + ty + r * 8) * SEQ_LEN + l0 + tx] = tile[tx][ty + r * 8];
}

__global__ void transpose_k() {
    __shared__ float tile[32][33];
    int l0 = blockIdx.x * 32, d0 = blockIdx.y * 32;
    int tx = threadIdx.x, ty = threadIdx.y;
#pragma unroll
    for (int r = 0; r < 4; r++)
        tile[ty + r * 8][tx] = g_k[(size_t)(l0 + ty + r * 8) * HIDDEN + d0 + tx];
    __syncthreads();
#pragma unroll
    for (int r = 0; r < 4; r++)
        g_kT[(size_t)(d0 + ty + r * 8) * SEQ_LEN + l0 + tx] = tile[tx][ty + r * 8];
}

__global__ void transpose_out(float* __restrict__ out) {
    __shared__ float tile[32][33];
    int b = blockIdx.z;
    int l0 = blockIdx.x * 32, d0 = blockIdx.y * 32;
    int tx = threadIdx.x, ty = threadIdx.y;
#pragma unroll
    for (int r = 0; r < 4; r++)
        tile[ty + r * 8][tx] = g_yT[(size_t)(b * HIDDEN + d0 + ty + r * 8) * SEQ_LEN + l0 + tx];
    __syncthreads();
    float* ob = out + (size_t)b * SEQ_LEN * HIDDEN;
#pragma unroll
    for (int r = 0; r < 4; r++)
        ob[(size_t)(l0 + ty + r * 8) * HIDDEN + d0 + tx] = tile[tx][ty + r * 8];
}

// ---------------- kernel spectrum ----------------
__global__ void __launch_bounds__(512, 2) kf_kernel() {
    extern __shared__ float2 S[];
    int d = blockIdx.x;
    int tid = threadIdx.x;
    const float2* krow = (const float2*)(g_kT + (size_t)d * SEQ_LEN);
    for (int n = tid; n < 4096; n += 512) S[PHYS(n)] = krow[n];
    for (int n = 4096 + tid; n < 8192; n += 512) S[PHYS(n)] = make_float2(0.f, 0.f);
    __syncthreads();
    fft_fwd(S, tid);

    const float invM = 1.0f / 16384.0f;
    float2* Kf = g_Kf + (size_t)d * (NFFT + 1);
    if (tid == 0) {
        float2 c0 = S[PHYS(0)];
        Kf[0]    = make_float2((c0.x + c0.y) * invM, 0.f);
        Kf[NFFT] = make_float2((c0.x - c0.y) * invM, 0.f);
    }
    for (int t = tid; t < 4096; t += 512) {
        int k  = t + 1;
        int p1 = __brev(k) >> 19;
        int p2 = __brev(8192 - k) >> 19;
        float2 C1 = S[PHYS(p1)], C2 = S[PHYS(p2)];
        float Ex = 0.5f * (C1.x + C2.x), Ey = 0.5f * (C1.y - C2.y);
        float Dx = C1.x - C2.x,          Dy = C1.y + C2.y;
        float Ox = 0.5f * Dy,            Oy = -0.5f * Dx;
        float2 w = g_tw[k];
        float wOx = Ox * w.x - Oy * w.y, wOy = Ox * w.y + Oy * w.x;
        Kf[k]        = make_float2((Ex + wOx) * invM, (Ey + wOy) * invM);
        Kf[8192 - k] = make_float2((Ex - wOx) * invM, -(Ey - wOy) * invM);
    }
}

// ---------------- fused conv ----------------
__global__ void __launch_bounds__(512, 2) conv_kernel(const float* __restrict__ bias) {
    extern __shared__ float2 S[];
    int col = blockIdx.x;           // b*768 + d
    int d   = col % HIDDEN;
    int tid = threadIdx.x;

    const float2* row = (const float2*)(g_xT + (size_t)col * SEQ_LEN);
    for (int n = tid; n < 4096; n += 512) S[PHYS(n)] = row[n];
    for (int n = 4096 + tid; n < 8192; n += 512) S[PHYS(n)] = make_float2(0.f, 0.f);
    __syncthreads();

    fft_fwd(S, tid);

    const float2* Kf = g_Kf + (size_t)d * (NFFT + 1);
    if (tid == 0) {
        float2 c0 = S[PHYS(0)];
        float U0 = c0.x + c0.y, UN = c0.x - c0.y;
        float2 F0 = Kf[0], FN = Kf[NFFT];
        float2 Y0 = make_float2(U0 * F0.x, U0 * F0.y);
        float2 YN = make_float2(UN * FN.x, UN * FN.y);
        float Eyx = 0.5f * (Y0.x + YN.x), Eyy = 0.5f * (Y0.y + YN.y);
        float Dyx = 0.5f * (Y0.x - YN.x), Dyy = 0.5f * (Y0.y - YN.y);
        S[PHYS(0)] = make_float2(Eyx - Dyy, Eyy + Dyx);
    }
    for (int t = tid; t < 4096; t += 512) {
        int k  = t + 1;
        int k2 = 8192 - k;
        int p1 = __brev(k)  >> 19;
        int p2 = __brev(k2) >> 19;
        int q1 = PHYS(p1), q2 = PHYS(p2);
        float2 C1 = S[q1], C2 = S[q2];
        float Ex = 0.5f * (C1.x + C2.x), Ey = 0.5f * (C1.y - C2.y);
        float Dx = C1.x - C2.x,          Dy = C1.y + C2.y;
        float Ox = 0.5f * Dy,            Oy = -0.5f * Dx;
        float2 w = g_tw[k];
        float wOx = Ox * w.x - Oy * w.y, wOy = Ox * w.y + Oy * w.x;
        float2 Uk  = make_float2(Ex + wOx, Ey + wOy);
        float2 UkN = make_float2(Ex - wOx, Ey - wOy);
        float2 F1 = Kf[k];
        float2 F2 = Kf[k2];
        float2 Y1 = cmul(Uk, F1);
        float2 Y2 = cmul(UkN, make_float2(F2.x, -F2.y));
        float2 Eyc = make_float2(0.5f * (Y1.x + Y2.x), 0.5f * (Y1.y + Y2.y));
        float2 Dyc = make_float2(0.5f * (Y1.x - Y2.x), 0.5f * (Y1.y - Y2.y));
        float2 Oyc = make_float2(Dyc.x * w.x + Dyc.y * w.y, Dyc.y * w.x - Dyc.x * w.y);
        float2 Zk  = make_float2(Eyc.x - Oyc.y, Eyc.y + Oyc.x);
        // mirror bin: w2 = g_tw[8192-k] = (-w.x, w.y)
        float2 Y1p = cmul(make_float2(UkN.x, -UkN.y), F2);
        float2 Y2p = cmul(make_float2(Uk.x, -Uk.y), make_float2(F1.x, -F1.y));
        float2 w2  = make_float2(-w.x, w.y);
        float2 Eyp = make_float2(0.5f * (Y1p.x + Y2p.x), 0.5f * (Y1p.y + Y2p.y));
        float2 Dyp = make_float2(0.5f * (Y1p.x - Y2p.x), 0.5f * (Y1p.y - Y2p.y));
        float2 Oyp = make_float2(Dyp.x * w2.x + Dyp.y * w2.y, Dyp.y * w2.x - Dyp.x * w2.y);
        float2 Zk2 = make_float2(Eyp.x - Oyp.y, Eyp.y + Oyp.x);
        S[q1] = Zk;
        S[q2] = Zk2;
    }
    __syncthreads();

    fft_inv(S, tid);

    const float invN = 1.0f / 8192.0f;
    float bv = bias[d];
    float2* orow = (float2*)(g_yT + (size_t)col * SEQ_LEN);
    for (int n = tid; n < 4096; n += 512) {
        float2 v = S[PHYS(n)];
        orow[n] = make_float2(v.x * invN + bv, v.y * invN + bv);
    }
}

// ---------------- launch ----------------
extern "C" void kernel_launch(void* const* d_in, const int* in_sizes, int n_in,
                              void* d_out, int out_size) {
    const float* x       = (const float*)d_in[0];
    const float* w_in    = (const float*)d_in[1];
    const float* b_in    = (const float*)d_in[2];
    const float* freq_in = (const float*)d_in[3];
    const float* w_h0    = (const float*)d_in[4];
    const float* b_h0    = (const float*)d_in[5];
    const float* freq_h0 = (const float*)d_in[6];
    const float* w_h1    = (const float*)d_in[7];
    const float* b_h1    = (const float*)d_in[8];
    const float* freq_h1 = (const float*)d_in[9];
    const float* w_out   = (const float*)d_in[10];
    const float* bias    = (const float*)d_in[11];
    float* out = (float*)d_out;

    cudaFuncSetAttribute(kf_kernel,   cudaFuncAttributeMaxDynamicSharedMemorySize, SMEM_BYTES);
    cudaFuncSetAttribute(conv_kernel, cudaFuncAttributeMaxDynamicSharedMemorySize, SMEM_BYTES);

    twiddle_init<<<16, 512>>>();
    filter_kernel<<<SEQ_LEN / 16, 256>>>(w_in, b_in, freq_in, w_h0, b_h0, freq_h0,
                                         w_h1, b_h1, freq_h1, w_out);
    dim3 tgrid(SEQ_LEN / 32, HIDDEN / 32, BATCH);
    dim3 tblk(32, 8);
    transpose_in<<<tgrid, tblk>>>(x);
    dim3 kgrid(SEQ_LEN / 32, HIDDEN / 32, 1);
    transpose_k<<<kgrid, tblk>>>();
    kf_kernel<<<HIDDEN, 512, SMEM_BYTES>>>();
    conv_kernel<<<BATCH * HIDDEN, 512, SMEM_BYTES>>>(bias);
    transpose_out<<<tgrid, tblk>>>(out);
}

// round 6
// speedup vs baseline: 3.8347x; 1.2852x over previous
#include <cuda_runtime.h>
#include <math.h>

#define SEQ_LEN 8192
#define HIDDEN  768
#define BATCH   8
#define NFFT    8192     // packed complex FFT size
#define MFFT    16384    // real FFT size
#define SMEM_BYTES (NFFT * 8)   // 65536

// ---------------- static scratch (allocation-free rule) ----------------
__device__ float2 g_tw[NFFT];                         // exp(-2*pi*i*k/16384)
__device__ float  g_k [SEQ_LEN * HIDDEN];             // filter (L, D)
__device__ float  g_kT[HIDDEN * SEQ_LEN];             // filter transposed (D, L)
__device__ float2 g_Kf[HIDDEN * (NFFT + 1)];          // rfft(k)/16384 per d
__device__ float  g_xT[BATCH * HIDDEN * SEQ_LEN];     // x transposed (B*D, L)
__device__ float  g_yT[BATCH * HIDDEN * SEQ_LEN];     // y transposed (B*D, L)

__device__ __forceinline__ float2 cmul(float2 a, float2 b) {
    return make_float2(a.x * b.x - a.y * b.y, a.x * b.y + a.y * b.x);
}
__device__ __forceinline__ float2 cmulc(float2 a, float2 b) {   // a * conj(b)
    return make_float2(a.x * b.x + a.y * b.y, a.y * b.x - a.x * b.y);
}
__device__ __forceinline__ float2 csq(float2 a) {
    return make_float2(a.x * a.x - a.y * a.y, 2.0f * a.x * a.y);
}
__device__ __forceinline__ float2 mulni(float2 a) {  // a * (-i)
    return make_float2(a.y, -a.x);
}
// XOR-swizzled physical index: conflict-free for strided FFT passes and
// 2-way worst case for the bit-reversed pointwise pass.
__device__ __forceinline__ int PHYS(int i) {
    return (i & ~15) | ((i ^ (i >> 4) ^ (i >> 8)) & 15);
}

// forward butterfly: a=u+v, b=(u-v)*w
#define FBF(a, b, w) { float2 u_=(a), v_=(b); (a)=make_float2(u_.x+v_.x,u_.y+v_.y); \
                       float2 d_=make_float2(u_.x-v_.x,u_.y-v_.y); (b)=cmul(d_, (w)); }
#define FBF1(a, b)   { float2 u_=(a), v_=(b); (a)=make_float2(u_.x+v_.x,u_.y+v_.y); \
                       (b)=make_float2(u_.x-v_.x,u_.y-v_.y); }
#define FBFNI(a, b)  { float2 u_=(a), v_=(b); (a)=make_float2(u_.x+v_.x,u_.y+v_.y); \
                       (b)=make_float2(u_.y-v_.y, -(u_.x-v_.x)); }
// inverse butterfly with FORWARD twiddle w (conj applied internally)
#define IBF(a, b, w) { float2 u_=(a); float2 tv_=cmulc((b),(w)); \
                       (a)=make_float2(u_.x+tv_.x,u_.y+tv_.y); (b)=make_float2(u_.x-tv_.x,u_.y-tv_.y); }
#define IBF1(a, b)   FBF1(a, b)
#define IBFPI(a, b)  { float2 u_=(a), v_=(b); float2 tv_=make_float2(-v_.y, v_.x); \
                       (a)=make_float2(u_.x+tv_.x,u_.y+tv_.y); (b)=make_float2(u_.x-tv_.x,u_.y-tv_.y); }

#define C8f 0.70710678118654752f
#define CAf 0.92387953251128676f
#define CBf 0.38268343236508977f

// ---------------- twiddle init ----------------
__global__ void twiddle_init() {
    int k = blockIdx.x * blockDim.x + threadIdx.x;
    if (k < NFFT) {
        double a = -2.0 * M_PI * (double)k / (double)MFFT;
        g_tw[k] = make_float2((float)cos(a), (float)sin(a));
    }
}

// ---------------- grouped forward stages s, s+1, s+2 (s in {0,3,6}) ----------------
template<int s>
__device__ __forceinline__ void fwd_group3(float2* S, int tid) {
    const int h = 1 << (10 - s);
#pragma unroll
    for (int it = 0; it < 2; it++) {
        int t = tid + it * 512;
        int r = t & (h - 1);
        int base = ((t >> (10 - s)) << (13 - s)) | r;
        float2 x[8];
#pragma unroll
        for (int e = 0; e < 8; e++) x[e] = S[PHYS(base + e * h)];
        float2 w1 = g_tw[r << (s + 1)];
        float2 w2 = csq(w1);
        float2 w4 = csq(w2);
        // stage s: pairs (e, e+4), w = w1 * exp(-i*pi*e/4)
        {
            float2 wr1 = cmul(w1, make_float2(C8f, -C8f));
            float2 wr2 = mulni(w1);
            float2 wr3 = cmul(w1, make_float2(-C8f, -C8f));
            FBF(x[0], x[4], w1);
            FBF(x[1], x[5], wr1);
            FBF(x[2], x[6], wr2);
            FBF(x[3], x[7], wr3);
        }
        // stage s+1: pairs (g+e, g+e+2), w = w2 * exp(-i*pi*e/2)
        {
            float2 w2n = mulni(w2);
            FBF(x[0], x[2], w2);
            FBF(x[1], x[3], w2n);
            FBF(x[4], x[6], w2);
            FBF(x[5], x[7], w2n);
        }
        // stage s+2: pairs (g, g+1), w = w4
        FBF(x[0], x[1], w4);
        FBF(x[2], x[3], w4);
        FBF(x[4], x[5], w4);
        FBF(x[6], x[7], w4);
#pragma unroll
        for (int e = 0; e < 8; e++) S[PHYS(base + e * h)] = x[e];
    }
}

// ---------------- forward stages 9..12 on 16 consecutive elements ----------------
__device__ __forceinline__ void fwd_group16(float2* S, int tid) {
    float2* row = S + tid * 16;
    int hh = (tid ^ (tid >> 4)) & 15;        // PHYS(16*tid + e) = 16*tid + (e ^ hh)
    float2 x[16];
#pragma unroll
    for (int e = 0; e < 16; e++) x[e] = row[e ^ hh];
    // stage 9: (e, e+8), w = exp(-i*pi*e/8)
    FBF1 (x[0], x[8]);
    FBF  (x[1], x[9],  make_float2( CAf, -CBf));
    FBF  (x[2], x[10], make_float2( C8f, -C8f));
    FBF  (x[3], x[11], make_float2( CBf, -CAf));
    FBFNI(x[4], x[12]);
    FBF  (x[5], x[13], make_float2(-CBf, -CAf));
    FBF  (x[6], x[14], make_float2(-C8f, -C8f));
    FBF  (x[7], x[15], make_float2(-CAf, -CBf));
    // stage 10: (g+e, g+e+4), w = exp(-i*pi*e/4)
#pragma unroll
    for (int g = 0; g < 16; g += 8) {
        FBF1 (x[g+0], x[g+4]);
        FBF  (x[g+1], x[g+5], make_float2( C8f, -C8f));
        FBFNI(x[g+2], x[g+6]);
        FBF  (x[g+3], x[g+7], make_float2(-C8f, -C8f));
    }
    // stage 11: (g+e, g+e+2), w = {1, -i}
#pragma unroll
    for (int g = 0; g < 16; g += 4) {
        FBF1 (x[g+0], x[g+2]);
        FBFNI(x[g+1], x[g+3]);
    }
    // stage 12: (g, g+1), w = 1
#pragma unroll
    for (int g = 0; g < 16; g += 2) FBF1(x[g], x[g+1]);
#pragma unroll
    for (int e = 0; e < 16; e++) row[e ^ hh] = x[e];
}

// ---------------- inverse stages 0..3 on 16 consecutive elements ----------------
__device__ __forceinline__ void inv_group16(float2* S, int tid) {
    float2* row = S + tid * 16;
    int hh = (tid ^ (tid >> 4)) & 15;
    float2 x[16];
#pragma unroll
    for (int e = 0; e < 16; e++) x[e] = row[e ^ hh];
    // stage 0: (g, g+1), w = 1
#pragma unroll
    for (int g = 0; g < 16; g += 2) IBF1(x[g], x[g+1]);
    // stage 1: (g+e, g+e+2), conj-tw = {1, +i}
#pragma unroll
    for (int g = 0; g < 16; g += 4) {
        IBF1 (x[g+0], x[g+2]);
        IBFPI(x[g+1], x[g+3]);
    }
    // stage 2: (g+e, g+e+4), fwd w = exp(-i*pi*e/4)
#pragma unroll
    for (int g = 0; g < 16; g += 8) {
        IBF1 (x[g+0], x[g+4]);
        IBF  (x[g+1], x[g+5], make_float2( C8f, -C8f));
        IBFPI(x[g+2], x[g+6]);
        IBF  (x[g+3], x[g+7], make_float2(-C8f, -C8f));
    }
    // stage 3: (e, e+8), fwd w = exp(-i*pi*e/8)
    IBF1 (x[0], x[8]);
    IBF  (x[1], x[9],  make_float2( CAf, -CBf));
    IBF  (x[2], x[10], make_float2( C8f, -C8f));
    IBF  (x[3], x[11], make_float2( CBf, -CAf));
    IBFPI(x[4], x[12]);
    IBF  (x[5], x[13], make_float2(-CBf, -CAf));
    IBF  (x[6], x[14], make_float2(-C8f, -C8f));
    IBF  (x[7], x[15], make_float2(-CAf, -CBf));
#pragma unroll
    for (int e = 0; e < 16; e++) row[e ^ hh] = x[e];
}

// ---------------- grouped inverse stages s0, s0+1, s0+2 (s0 in {4,7,10}) -------
template<int s0>
__device__ __forceinline__ void inv_group3(float2* S, int tid) {
    const int h = 1 << s0;
#pragma unroll
    for (int it = 0; it < 2; it++) {
        int t = tid + it * 512;
        int r = t & (h - 1);
        int base = ((t >> s0) << (s0 + 3)) | r;
        float2 x[8];
#pragma unroll
        for (int e = 0; e < 8; e++) x[e] = S[PHYS(base + e * h)];
        float2 wB = g_tw[r << (11 - s0)];
        float2 wB2 = csq(wB);
        float2 wB4 = csq(wB2);
        // stage s0: pairs (g, g+1), fwd w = wB4
        IBF(x[0], x[1], wB4);
        IBF(x[2], x[3], wB4);
        IBF(x[4], x[5], wB4);
        IBF(x[6], x[7], wB4);
        // stage s0+1: pairs (g+e, g+e+2), fwd w = wB2 * exp(-i*pi*e/2)
        {
            float2 w2n = mulni(wB2);
            IBF(x[0], x[2], wB2);
            IBF(x[1], x[3], w2n);
            IBF(x[4], x[6], wB2);
            IBF(x[5], x[7], w2n);
        }
        // stage s0+2: pairs (e, e+4), fwd w = wB * exp(-i*pi*e/4)
        {
            float2 wr1 = cmul(wB, make_float2(C8f, -C8f));
            float2 wr2 = mulni(wB);
            float2 wr3 = cmul(wB, make_float2(-C8f, -C8f));
            IBF(x[0], x[4], wB);
            IBF(x[1], x[5], wr1);
            IBF(x[2], x[6], wr2);
            IBF(x[3], x[7], wr3);
        }
#pragma unroll
        for (int e = 0; e < 8; e++) S[PHYS(base + e * h)] = x[e];
    }
}

__device__ __forceinline__ void fft_fwd(float2* S, int tid) {
    fwd_group3<0>(S, tid); __syncthreads();
    fwd_group3<3>(S, tid); __syncthreads();
    fwd_group3<6>(S, tid); __syncthreads();
    fwd_group16(S, tid);   __syncthreads();
}
__device__ __forceinline__ void fft_inv(float2* S, int tid) {
    inv_group16(S, tid);   __syncthreads();
    inv_group3<4>(S, tid); __syncthreads();
    inv_group3<7>(S, tid); __syncthreads();
    inv_group3<10>(S, tid); __syncthreads();
}

// ---------------- implicit filter MLP + modulation ----------------
__global__ void filter_kernel(
    const float* __restrict__ w_in,  const float* __restrict__ b_in,  const float* __restrict__ freq_in,
    const float* __restrict__ w_h0,  const float* __restrict__ b_h0,  const float* __restrict__ freq_h0,
    const float* __restrict__ w_h1,  const float* __restrict__ b_h1,  const float* __restrict__ freq_h1,
    const float* __restrict__ w_out)
{
    __shared__ float hA[16][64];
    __shared__ float hB[16][64];
    int l0 = blockIdx.x * 16;
    int tid = threadIdx.x;

    for (int idx = tid; idx < 16 * 64; idx += 256) {
        int ll = idx >> 6, j = idx & 63;
        int l = l0 + ll;
        float t0 = (float)l / (float)(SEQ_LEN - 1);
        float ang = (float)(2.0 * M_PI * 1e-4 / (double)SEQ_LEN) * (float)l;
        float z1 = cosf(ang), z2 = -sinf(ang);
        float v = t0 * w_in[j] + z1 * w_in[64 + j] + z2 * w_in[128 + j] + b_in[j];
        hA[ll][j] = sinf(freq_in[j] * v);
    }
    __syncthreads();
    for (int idx = tid; idx < 16 * 64; idx += 256) {
        int ll = idx >> 6, j = idx & 63;
        float acc = b_h0[j];
#pragma unroll
        for (int i = 0; i < 64; i++) acc += hA[ll][i] * w_h0[i * 64 + j];
        hB[ll][j] = sinf(freq_h0[j] * acc);
    }
    __syncthreads();
    for (int idx = tid; idx < 16 * 64; idx += 256) {
        int ll = idx >> 6, j = idx & 63;
        float acc = b_h1[j];
#pragma unroll
        for (int i = 0; i < 64; i++) acc += hB[ll][i] * w_h1[i * 64 + j];
        hA[ll][j] = sinf(freq_h1[j] * acc);
    }
    __syncthreads();

    const float MIND = 3.0701134573253943f;
    const float MAXD = 15.350567286626972f;
    for (int ll = 0; ll < 16; ll++) {
        int l = l0 + ll;
        float t0 = (float)l / (float)(SEQ_LEN - 1);
        for (int d = tid; d < HIDDEN; d += 256) {
            float acc = 0.f;
#pragma unroll
            for (int i = 0; i < 64; i++) acc += hA[ll][i] * w_out[i * HIDDEN + d];
            float ad = MIND + (MAXD - MIND) * ((float)d / 767.0f);
            g_k[(size_t)l * HIDDEN + d] = acc * expf(-t0 * ad);
        }
    }
}

// ---------------- transposes ----------------
__global__ void transpose_in(const float* __restrict__ x) {
    __shared__ float tile[32][33];
    int b = blockIdx.z;
    int l0 = blockIdx.x * 32, d0 = blockIdx.y * 32;
    int tx = threadIdx.x, ty = threadIdx.y; // (32, 8)
    const float* xb = x + (size_t)b * SEQ_LEN * HIDDEN;
#pragma unroll
    for (int r = 0; r < 4; r++)
        tile[ty + r * 8][tx] = xb[(size_t)(l0 + ty + r * 8) * HIDDEN + d0 + tx];
    __syncthreads();
#pragma unroll
    for (int r = 0; r < 4; r++)
        g_xT[(size_t)(b * HIDDEN + d0 + ty + r * 8) * SEQ_LEN + l0 + tx] = tile[tx][ty + r * 8];
}

__global__ void transpose_k() {
    __shared__ float tile[32][33];
    int l0 = blockIdx.x * 32, d0 = blockIdx.y * 32;
    int tx = threadIdx.x, ty = threadIdx.y;
#pragma unroll
    for (int r = 0; r < 4; r++)
        tile[ty + r * 8][tx] = g_k[(size_t)(l0 + ty + r * 8) * HIDDEN + d0 + tx];
    __syncthreads();
#pragma unroll
    for (int r = 0; r < 4; r++)
        g_kT[(size_t)(d0 + ty + r * 8) * SEQ_LEN + l0 + tx] = tile[tx][ty + r * 8];
}

__global__ void transpose_out(float* __restrict__ out) {
    __shared__ float tile[32][33];
    int b = blockIdx.z;
    int l0 = blockIdx.x * 32, d0 = blockIdx.y * 32;
    int tx = threadIdx.x, ty = threadIdx.y;
#pragma unroll
    for (int r = 0; r < 4; r++)
        tile[ty + r * 8][tx] = g_yT[(size_t)(b * HIDDEN + d0 + ty + r * 8) * SEQ_LEN + l0 + tx];
    __syncthreads();
    float* ob = out + (size_t)b * SEQ_LEN * HIDDEN;
#pragma unroll
    for (int r = 0; r < 4; r++)
        ob[(size_t)(l0 + ty + r * 8) * HIDDEN + d0 + tx] = tile[tx][ty + r * 8];
}

// ---------------- kernel spectrum ----------------
__global__ void __launch_bounds__(512, 3) kf_kernel() {
    extern __shared__ float2 S[];
    int d = blockIdx.x;
    int tid = threadIdx.x;
    const float2* krow = (const float2*)(g_kT + (size_t)d * SEQ_LEN);
    for (int n = tid; n < 4096; n += 512) S[PHYS(n)] = krow[n];
    for (int n = 4096 + tid; n < 8192; n += 512) S[PHYS(n)] = make_float2(0.f, 0.f);
    __syncthreads();
    fft_fwd(S, tid);

    const float invM = 1.0f / 16384.0f;
    float2* Kf = g_Kf + (size_t)d * (NFFT + 1);
    if (tid == 0) {
        float2 c0 = S[PHYS(0)];
        Kf[0]    = make_float2((c0.x + c0.y) * invM, 0.f);
        Kf[NFFT] = make_float2((c0.x - c0.y) * invM, 0.f);
    }
    for (int t = tid; t < 4096; t += 512) {
        int k  = t + 1;
        int p1 = __brev(k) >> 19;
        int p2 = __brev(8192 - k) >> 19;
        float2 C1 = S[PHYS(p1)], C2 = S[PHYS(p2)];
        float Ex = 0.5f * (C1.x + C2.x), Ey = 0.5f * (C1.y - C2.y);
        float Dx = C1.x - C2.x,          Dy = C1.y + C2.y;
        float Ox = 0.5f * Dy,            Oy = -0.5f * Dx;
        float2 w = g_tw[k];
        float wOx = Ox * w.x - Oy * w.y, wOy = Ox * w.y + Oy * w.x;
        Kf[k]        = make_float2((Ex + wOx) * invM, (Ey + wOy) * invM);
        Kf[8192 - k] = make_float2((Ex - wOx) * invM, -(Ey - wOy) * invM);
    }
}

// ---------------- fused conv ----------------
__global__ void __launch_bounds__(512, 3) conv_kernel(const float* __restrict__ bias) {
    extern __shared__ float2 S[];
    int col = blockIdx.x;           // b*768 + d
    int d   = col % HIDDEN;
    int tid = threadIdx.x;

    const float2* row = (const float2*)(g_xT + (size_t)col * SEQ_LEN);
    for (int n = tid; n < 4096; n += 512) S[PHYS(n)] = row[n];
    for (int n = 4096 + tid; n < 8192; n += 512) S[PHYS(n)] = make_float2(0.f, 0.f);
    __syncthreads();

    fft_fwd(S, tid);

    const float2* Kf = g_Kf + (size_t)d * (NFFT + 1);
    if (tid == 0) {
        float2 c0 = S[PHYS(0)];
        float U0 = c0.x + c0.y, UN = c0.x - c0.y;
        float2 F0 = Kf[0], FN = Kf[NFFT];
        float2 Y0 = make_float2(U0 * F0.x, U0 * F0.y);
        float2 YN = make_float2(UN * FN.x, UN * FN.y);
        float Eyx = 0.5f * (Y0.x + YN.x), Eyy = 0.5f * (Y0.y + YN.y);
        float Dyx = 0.5f * (Y0.x - YN.x), Dyy = 0.5f * (Y0.y - YN.y);
        S[PHYS(0)] = make_float2(Eyx - Dyy, Eyy + Dyx);
    }
    for (int t = tid; t < 4096; t += 512) {
        int k  = t + 1;
        int k2 = 8192 - k;
        int p1 = __brev(k)  >> 19;
        int p2 = __brev(k2) >> 19;
        int q1 = PHYS(p1), q2 = PHYS(p2);
        float2 C1 = S[q1], C2 = S[q2];
        float Ex = 0.5f * (C1.x + C2.x), Ey = 0.5f * (C1.y - C2.y);
        float Dx = C1.x - C2.x,          Dy = C1.y + C2.y;
        float Ox = 0.5f * Dy,            Oy = -0.5f * Dx;
        float2 w = g_tw[k];
        float wOx = Ox * w.x - Oy * w.y, wOy = Ox * w.y + Oy * w.x;
        float2 Uk  = make_float2(Ex + wOx, Ey + wOy);
        float2 UkN = make_float2(Ex - wOx, Ey - wOy);
        float2 F1 = Kf[k];
        float2 F2 = Kf[k2];
        float2 Y1 = cmul(Uk, F1);
        float2 Y2 = cmul(UkN, make_float2(F2.x, -F2.y));
        float2 Eyc = make_float2(0.5f * (Y1.x + Y2.x), 0.5f * (Y1.y + Y2.y));
        float2 Dyc = make_float2(0.5f * (Y1.x - Y2.x), 0.5f * (Y1.y - Y2.y));
        float2 Oyc = make_float2(Dyc.x * w.x + Dyc.y * w.y, Dyc.y * w.x - Dyc.x * w.y);
        float2 Zk  = make_float2(Eyc.x - Oyc.y, Eyc.y + Oyc.x);
        // mirror bin: w2 = g_tw[8192-k] = (-w.x, w.y)
        float2 Y1p = cmul(make_float2(UkN.x, -UkN.y), F2);
        float2 Y2p = cmul(make_float2(Uk.x, -Uk.y), make_float2(F1.x, -F1.y));
        float2 w2  = make_float2(-w.x, w.y);
        float2 Eyp = make_float2(0.5f * (Y1p.x + Y2p.x), 0.5f * (Y1p.y + Y2p.y));
        float2 Dyp = make_float2(0.5f * (Y1p.x - Y2p.x), 0.5f * (Y1p.y - Y2p.y));
        float2 Oyp = make_float2(Dyp.x * w2.x + Dyp.y * w2.y, Dyp.y * w2.x - Dyp.x * w2.y);
        float2 Zk2 = make_float2(Eyp.x - Oyp.y, Eyp.y + Oyp.x);
        S[q1] = Zk;
        S[q2] = Zk2;
    }
    __syncthreads();

    fft_inv(S, tid);

    const float invN = 1.0f / 8192.0f;
    float bv = bias[d];
    float2* orow = (float2*)(g_yT + (size_t)col * SEQ_LEN);
    for (int n = tid; n < 4096; n += 512) {
        float2 v = S[PHYS(n)];
        orow[n] = make_float2(v.x * invN + bv, v.y * invN + bv);
    }
}

// ---------------- launch ----------------
extern "C" void kernel_launch(void* const* d_in, const int* in_sizes, int n_in,
                              void* d_out, int out_size) {
    const float* x       = (const float*)d_in[0];
    const float* w_in    = (const float*)d_in[1];
    const float* b_in    = (const float*)d_in[2];
    const float* freq_in = (const float*)d_in[3];
    const float* w_h0    = (const float*)d_in[4];
    const float* b_h0    = (const float*)d_in[5];
    const float* freq_h0 = (const float*)d_in[6];
    const float* w_h1    = (const float*)d_in[7];
    const float* b_h1    = (const float*)d_in[8];
    const float* freq_h1 = (const float*)d_in[9];
    const float* w_out   = (const float*)d_in[10];
    const float* bias    = (const float*)d_in[11];
    float* out = (float*)d_out;

    cudaFuncSetAttribute(kf_kernel,   cudaFuncAttributeMaxDynamicSharedMemorySize, SMEM_BYTES);
    cudaFuncSetAttribute(conv_kernel, cudaFuncAttributeMaxDynamicSharedMemorySize, SMEM_BYTES);

    twiddle_init<<<16, 512>>>();
    filter_kernel<<<SEQ_LEN / 16, 256>>>(w_in, b_in, freq_in, w_h0, b_h0, freq_h0,
                                         w_h1, b_h1, freq_h1, w_out);
    dim3 tgrid(SEQ_LEN / 32, HIDDEN / 32, BATCH);
    dim3 tblk(32, 8);
    transpose_in<<<tgrid, tblk>>>(x);
    dim3 kgrid(SEQ_LEN / 32, HIDDEN / 32, 1);
    transpose_k<<<kgrid, tblk>>>();
    kf_kernel<<<HIDDEN, 512, SMEM_BYTES>>>();
    conv_kernel<<<BATCH * HIDDEN, 512, SMEM_BYTES>>>(bias);
    transpose_out<<<tgrid, tblk>>>(out);
}

// round 8
// speedup vs baseline: 4.3009x; 1.1216x over previous
#include <cuda_runtime.h>
#include <math.h>

#define SEQ_LEN 8192
#define HIDDEN  768
#define BATCH   8
#define NFFT    8192     // packed complex FFT size
#define MFFT    16384    // real FFT size
#define SMEM_BYTES (NFFT * 8)   // 65536

// ---------------- static scratch (allocation-free rule) ----------------
__device__ float2 g_tw[NFFT];                         // exp(-2*pi*i*k/16384)
__device__ float  g_k [SEQ_LEN * HIDDEN];             // filter (L, D)
__device__ float  g_kT[HIDDEN * SEQ_LEN];             // filter transposed (D, L)
__device__ float2 g_Kf[HIDDEN * (NFFT + 1)];          // rfft(k)/16384 per d
__device__ float  g_xT[BATCH * HIDDEN * SEQ_LEN];     // x transposed (B*D, L)
__device__ float  g_yT[BATCH * HIDDEN * SEQ_LEN];     // y transposed (B*D, L)

__device__ __forceinline__ float2 cmul(float2 a, float2 b) {
    return make_float2(a.x * b.x - a.y * b.y, a.x * b.y + a.y * b.x);
}
__device__ __forceinline__ float2 cmulc(float2 a, float2 b) {   // a * conj(b)
    return make_float2(a.x * b.x + a.y * b.y, a.y * b.x - a.x * b.y);
}
__device__ __forceinline__ float2 csq(float2 a) {
    return make_float2(a.x * a.x - a.y * a.y, 2.0f * a.x * a.y);
}
__device__ __forceinline__ float2 mulni(float2 a) {  // a * (-i)
    return make_float2(a.y, -a.x);
}
// XOR-swizzled physical index: conflict-free for strided FFT passes and
// 2-way worst case for the bit-reversed pointwise pass.
__device__ __forceinline__ int PHYS(int i) {
    return (i & ~15) | ((i ^ (i >> 4) ^ (i >> 8)) & 15);
}

// forward butterfly: a=u+v, b=(u-v)*w
#define FBF(a, b, w) { float2 u_=(a), v_=(b); (a)=make_float2(u_.x+v_.x,u_.y+v_.y); \
                       float2 d_=make_float2(u_.x-v_.x,u_.y-v_.y); (b)=cmul(d_, (w)); }
#define FBF1(a, b)   { float2 u_=(a), v_=(b); (a)=make_float2(u_.x+v_.x,u_.y+v_.y); \
                       (b)=make_float2(u_.x-v_.x,u_.y-v_.y); }
#define FBFNI(a, b)  { float2 u_=(a), v_=(b); (a)=make_float2(u_.x+v_.x,u_.y+v_.y); \
                       (b)=make_float2(u_.y-v_.y, -(u_.x-v_.x)); }
// inverse butterfly with FORWARD twiddle w (conj applied internally)
#define IBF(a, b, w) { float2 u_=(a); float2 tv_=cmulc((b),(w)); \
                       (a)=make_float2(u_.x+tv_.x,u_.y+tv_.y); (b)=make_float2(u_.x-tv_.x,u_.y-tv_.y); }
#define IBF1(a, b)   FBF1(a, b)
#define IBFPI(a, b)  { float2 u_=(a), v_=(b); float2 tv_=make_float2(-v_.y, v_.x); \
                       (a)=make_float2(u_.x+tv_.x,u_.y+tv_.y); (b)=make_float2(u_.x-tv_.x,u_.y-tv_.y); }

#define C8f 0.70710678118654752f
#define CAf 0.92387953251128676f
#define CBf 0.38268343236508977f

// ---------------- twiddle init ----------------
__global__ void twiddle_init() {
    int k = blockIdx.x * blockDim.x + threadIdx.x;
    if (k < NFFT) {
        double a = -2.0 * M_PI * (double)k / (double)MFFT;
        g_tw[k] = make_float2((float)cos(a), (float)sin(a));
    }
}

// ---------------- fused forward pass 1 (stages 0,1,2): global load + zero pad ----
// Upper half of the 8192 logical input is zero, so stage 0 butterflies reduce to
// x[e+4] = x[e]*w. Reads the 4 live elements straight from global memory.
__device__ __forceinline__ void fwd_pass1_fused(float2* S, int tid, const float2* __restrict__ g) {
#pragma unroll
    for (int it = 0; it < 2; it++) {
        int t = tid + it * 512;           // base = t, r = t
        float2 x[8];
#pragma unroll
        for (int e = 0; e < 4; e++) x[e] = g[t + e * 1024];
        float2 w1 = g_tw[t << 1];
        float2 w2 = csq(w1);
        float2 w4 = csq(w2);
        // stage 0 with zero upper half
        {
            float2 wr1 = cmul(w1, make_float2(C8f, -C8f));
            float2 wr2 = mulni(w1);
            float2 wr3 = cmul(w1, make_float2(-C8f, -C8f));
            x[4] = cmul(x[0], w1);
            x[5] = cmul(x[1], wr1);
            x[6] = cmul(x[2], wr2);
            x[7] = cmul(x[3], wr3);
        }
        // stage 1
        {
            float2 w2n = mulni(w2);
            FBF(x[0], x[2], w2);
            FBF(x[1], x[3], w2n);
            FBF(x[4], x[6], w2);
            FBF(x[5], x[7], w2n);
        }
        // stage 2
        FBF(x[0], x[1], w4);
        FBF(x[2], x[3], w4);
        FBF(x[4], x[5], w4);
        FBF(x[6], x[7], w4);
#pragma unroll
        for (int e = 0; e < 8; e++) S[PHYS(t + e * 1024)] = x[e];
    }
}

// ---------------- grouped forward stages s, s+1, s+2 (s in {3,6}) ----------------
template<int s>
__device__ __forceinline__ void fwd_group3(float2* S, int tid) {
    const int h = 1 << (10 - s);
#pragma unroll
    for (int it = 0; it < 2; it++) {
        int t = tid + it * 512;
        int r = t & (h - 1);
        int base = ((t >> (10 - s)) << (13 - s)) | r;
        float2 x[8];
#pragma unroll
        for (int e = 0; e < 8; e++) x[e] = S[PHYS(base + e * h)];
        float2 w1 = g_tw[r << (s + 1)];
        float2 w2 = csq(w1);
        float2 w4 = csq(w2);
        {
            float2 wr1 = cmul(w1, make_float2(C8f, -C8f));
            float2 wr2 = mulni(w1);
            float2 wr3 = cmul(w1, make_float2(-C8f, -C8f));
            FBF(x[0], x[4], w1);
            FBF(x[1], x[5], wr1);
            FBF(x[2], x[6], wr2);
            FBF(x[3], x[7], wr3);
        }
        {
            float2 w2n = mulni(w2);
            FBF(x[0], x[2], w2);
            FBF(x[1], x[3], w2n);
            FBF(x[4], x[6], w2);
            FBF(x[5], x[7], w2n);
        }
        FBF(x[0], x[1], w4);
        FBF(x[2], x[3], w4);
        FBF(x[4], x[5], w4);
        FBF(x[6], x[7], w4);
#pragma unroll
        for (int e = 0; e < 8; e++) S[PHYS(base + e * h)] = x[e];
    }
}

// ---------------- forward stages 9..12 on 16 consecutive elements ----------------
__device__ __forceinline__ void fwd_group16(float2* S, int tid) {
    float2* row = S + tid * 16;
    int hh = (tid ^ (tid >> 4)) & 15;        // PHYS(16*tid + e) = 16*tid + (e ^ hh)
    float2 x[16];
#pragma unroll
    for (int e = 0; e < 16; e++) x[e] = row[e ^ hh];
    // stage 9: (e, e+8), w = exp(-i*pi*e/8)
    FBF1 (x[0], x[8]);
    FBF  (x[1], x[9],  make_float2( CAf, -CBf));
    FBF  (x[2], x[10], make_float2( C8f, -C8f));
    FBF  (x[3], x[11], make_float2( CBf, -CAf));
    FBFNI(x[4], x[12]);
    FBF  (x[5], x[13], make_float2(-CBf, -CAf));
    FBF  (x[6], x[14], make_float2(-C8f, -C8f));
    FBF  (x[7], x[15], make_float2(-CAf, -CBf));
    // stage 10: (g+e, g+e+4), w = exp(-i*pi*e/4)
#pragma unroll
    for (int g = 0; g < 16; g += 8) {
        FBF1 (x[g+0], x[g+4]);
        FBF  (x[g+1], x[g+5], make_float2( C8f, -C8f));
        FBFNI(x[g+2], x[g+6]);
        FBF  (x[g+3], x[g+7], make_float2(-C8f, -C8f));
    }
    // stage 11: (g+e, g+e+2), w = {1, -i}
#pragma unroll
    for (int g = 0; g < 16; g += 4) {
        FBF1 (x[g+0], x[g+2]);
        FBFNI(x[g+1], x[g+3]);
    }
    // stage 12: (g, g+1), w = 1
#pragma unroll
    for (int g = 0; g < 16; g += 2) FBF1(x[g], x[g+1]);
#pragma unroll
    for (int e = 0; e < 16; e++) row[e ^ hh] = x[e];
}

// ---------------- inverse stages 0..3 on 16 consecutive elements ----------------
__device__ __forceinline__ void inv_group16(float2* S, int tid) {
    float2* row = S + tid * 16;
    int hh = (tid ^ (tid >> 4)) & 15;
    float2 x[16];
#pragma unroll
    for (int e = 0; e < 16; e++) x[e] = row[e ^ hh];
#pragma unroll
    for (int g = 0; g < 16; g += 2) IBF1(x[g], x[g+1]);
#pragma unroll
    for (int g = 0; g < 16; g += 4) {
        IBF1 (x[g+0], x[g+2]);
        IBFPI(x[g+1], x[g+3]);
    }
#pragma unroll
    for (int g = 0; g < 16; g += 8) {
        IBF1 (x[g+0], x[g+4]);
        IBF  (x[g+1], x[g+5], make_float2( C8f, -C8f));
        IBFPI(x[g+2], x[g+6]);
        IBF  (x[g+3], x[g+7], make_float2(-C8f, -C8f));
    }
    IBF1 (x[0], x[8]);
    IBF  (x[1], x[9],  make_float2( CAf, -CBf));
    IBF  (x[2], x[10], make_float2( C8f, -C8f));
    IBF  (x[3], x[11], make_float2( CBf, -CAf));
    IBFPI(x[4], x[12]);
    IBF  (x[5], x[13], make_float2(-CBf, -CAf));
    IBF  (x[6], x[14], make_float2(-C8f, -C8f));
    IBF  (x[7], x[15], make_float2(-CAf, -CBf));
#pragma unroll
    for (int e = 0; e < 16; e++) row[e ^ hh] = x[e];
}

// ---------------- grouped inverse stages s0, s0+1, s0+2 (s0 in {4,7}) -------
template<int s0>
__device__ __forceinline__ void inv_group3(float2* S, int tid) {
    const int h = 1 << s0;
#pragma unroll
    for (int it = 0; it < 2; it++) {
        int t = tid + it * 512;
        int r = t & (h - 1);
        int base = ((t >> s0) << (s0 + 3)) | r;
        float2 x[8];
#pragma unroll
        for (int e = 0; e < 8; e++) x[e] = S[PHYS(base + e * h)];
        float2 wB = g_tw[r << (11 - s0)];
        float2 wB2 = csq(wB);
        float2 wB4 = csq(wB2);
        IBF(x[0], x[1], wB4);
        IBF(x[2], x[3], wB4);
        IBF(x[4], x[5], wB4);
        IBF(x[6], x[7], wB4);
        {
            float2 w2n = mulni(wB2);
            IBF(x[0], x[2], wB2);
            IBF(x[1], x[3], w2n);
            IBF(x[4], x[6], wB2);
            IBF(x[5], x[7], w2n);
        }
        {
            float2 wr1 = cmul(wB, make_float2(C8f, -C8f));
            float2 wr2 = mulni(wB);
            float2 wr3 = cmul(wB, make_float2(-C8f, -C8f));
            IBF(x[0], x[4], wB);
            IBF(x[1], x[5], wr1);
            IBF(x[2], x[6], wr2);
            IBF(x[3], x[7], wr3);
        }
#pragma unroll
        for (int e = 0; e < 8; e++) S[PHYS(base + e * h)] = x[e];
    }
}

// ---------------- fused inverse final pass (stages 10,11,12) --------------------
// Only natural-order outputs 0..4095 (e < 4) are kept: compute only the lower
// half-butterfly of the last stage, apply scale+bias, store 4 float2/thread/iter.
__device__ __forceinline__ void inv_pass4_fused(float2* S, int tid,
                                                float2* __restrict__ gdst,
                                                float scale, float bv) {
#pragma unroll
    for (int it = 0; it < 2; it++) {
        int t = tid + it * 512;           // base = t, r = t (s0 = 10)
        float2 x[8];
#pragma unroll
        for (int e = 0; e < 8; e++) x[e] = S[PHYS(t + e * 1024)];
        float2 wB = g_tw[t << 1];
        float2 wB2 = csq(wB);
        float2 wB4 = csq(wB2);
        // stage 10: pairs (g, g+1)
        IBF(x[0], x[1], wB4);
        IBF(x[2], x[3], wB4);
        IBF(x[4], x[5], wB4);
        IBF(x[6], x[7], wB4);
        // stage 11: pairs (g+e, g+e+2)
        {
            float2 w2n = mulni(wB2);
            IBF(x[0], x[2], wB2);
            IBF(x[1], x[3], w2n);
            IBF(x[4], x[6], wB2);
            IBF(x[5], x[7], w2n);
        }
        // stage 12: pairs (e, e+4) — only lower outputs needed
        {
            float2 wr1 = cmul(wB, make_float2(C8f, -C8f));
            float2 wr2 = mulni(wB);
            float2 wr3 = cmul(wB, make_float2(-C8f, -C8f));
            float2 t0 = cmulc(x[4], wB);
            float2 t1 = cmulc(x[5], wr1);
            float2 t2 = cmulc(x[6], wr2);
            float2 t3 = cmulc(x[7], wr3);
            x[0] = make_float2(x[0].x + t0.x, x[0].y + t0.y);
            x[1] = make_float2(x[1].x + t1.x, x[1].y + t1.y);
            x[2] = make_float2(x[2].x + t2.x, x[2].y + t2.y);
            x[3] = make_float2(x[3].x + t3.x, x[3].y + t3.y);
        }
#pragma unroll
        for (int e = 0; e < 4; e++)
            gdst[t + e * 1024] = make_float2(x[e].x * scale + bv, x[e].y * scale + bv);
    }
}

// ---------------- implicit filter MLP + modulation ----------------
__global__ void filter_kernel(
    const float* __restrict__ w_in,  const float* __restrict__ b_in,  const float* __restrict__ freq_in,
    const float* __restrict__ w_h0,  const float* __restrict__ b_h0,  const float* __restrict__ freq_h0,
    const float* __restrict__ w_h1,  const float* __restrict__ b_h1,  const float* __restrict__ freq_h1,
    const float* __restrict__ w_out)
{
    __shared__ float hA[16][64];
    __shared__ float hB[16][64];
    int l0 = blockIdx.x * 16;
    int tid = threadIdx.x;

    for (int idx = tid; idx < 16 * 64; idx += 256) {
        int ll = idx >> 6, j = idx & 63;
        int l = l0 + ll;
        float t0 = (float)l / (float)(SEQ_LEN - 1);
        float ang = (float)(2.0 * M_PI * 1e-4 / (double)SEQ_LEN) * (float)l;
        float z1 = cosf(ang), z2 = -sinf(ang);
        float v = t0 * w_in[j] + z1 * w_in[64 + j] + z2 * w_in[128 + j] + b_in[j];
        hA[ll][j] = sinf(freq_in[j] * v);
    }
    __syncthreads();
    for (int idx = tid; idx < 16 * 64; idx += 256) {
        int ll = idx >> 6, j = idx & 63;
        float acc = b_h0[j];
#pragma unroll
        for (int i = 0; i < 64; i++) acc += hA[ll][i] * w_h0[i * 64 + j];
        hB[ll][j] = sinf(freq_h0[j] * acc);
    }
    __syncthreads();
    for (int idx = tid; idx < 16 * 64; idx += 256) {
        int ll = idx >> 6, j = idx & 63;
        float acc = b_h1[j];
#pragma unroll
        for (int i = 0; i < 64; i++) acc += hB[ll][i] * w_h1[i * 64 + j];
        hA[ll][j] = sinf(freq_h1[j] * acc);
    }
    __syncthreads();

    const float MIND = 3.0701134573253943f;
    const float MAXD = 15.350567286626972f;
    for (int ll = 0; ll < 16; ll++) {
        int l = l0 + ll;
        float t0 = (float)l / (float)(SEQ_LEN - 1);
        for (int d = tid; d < HIDDEN; d += 256) {
            float acc = 0.f;
#pragma unroll
            for (int i = 0; i < 64; i++) acc += hA[ll][i] * w_out[i * HIDDEN + d];
            float ad = MIND + (MAXD - MIND) * ((float)d / 767.0f);
            g_k[(size_t)l * HIDDEN + d] = acc * expf(-t0 * ad);
        }
    }
}

// ---------------- transposes: 128(l) x 32(d) per block, MLP=16 ----------------
__device__ __forceinline__ void transpose_LD_DL_body(const float* __restrict__ s,
                                                     float* __restrict__ dd,
                                                     int l0, int d0, int tx, int ty) {
    __shared__ float tile[4][32][33];
#pragma unroll
    for (int st = 0; st < 4; st++)
#pragma unroll
        for (int r = 0; r < 4; r++)
            tile[st][ty + r * 8][tx] =
                s[(size_t)(l0 + st * 32 + ty + r * 8) * HIDDEN + d0 + tx];
    __syncthreads();
#pragma unroll
    for (int st = 0; st < 4; st++)
#pragma unroll
        for (int r = 0; r < 4; r++)
            dd[(size_t)(d0 + ty + r * 8) * SEQ_LEN + l0 + st * 32 + tx] =
                tile[st][tx][ty + r * 8];
}

__global__ void transpose_in(const float* __restrict__ x) {
    int b = blockIdx.z;
    transpose_LD_DL_body(x + (size_t)b * SEQ_LEN * HIDDEN,
                         g_xT + (size_t)b * HIDDEN * SEQ_LEN,
                         blockIdx.x * 128, blockIdx.y * 32, threadIdx.x, threadIdx.y);
}

__global__ void transpose_k() {
    transpose_LD_DL_body(g_k, g_kT, blockIdx.x * 128, blockIdx.y * 32,
                         threadIdx.x, threadIdx.y);
}

__global__ void transpose_out(float* __restrict__ out) {
    __shared__ float tile[4][32][33];
    int b = blockIdx.z;
    int l0 = blockIdx.x * 128, d0 = blockIdx.y * 32;
    int tx = threadIdx.x, ty = threadIdx.y;
    const float* s = g_yT + (size_t)b * HIDDEN * SEQ_LEN;
    float* dd = out + (size_t)b * SEQ_LEN * HIDDEN;
#pragma unroll
    for (int st = 0; st < 4; st++)
#pragma unroll
        for (int r = 0; r < 4; r++)
            tile[st][ty + r * 8][tx] =
                s[(size_t)(d0 + ty + r * 8) * SEQ_LEN + l0 + st * 32 + tx];
    __syncthreads();
#pragma unroll
    for (int st = 0; st < 4; st++)
#pragma unroll
        for (int r = 0; r < 4; r++)
            dd[(size_t)(l0 + st * 32 + ty + r * 8) * HIDDEN + d0 + tx] =
                tile[st][tx][ty + r * 8];
}

// ---------------- kernel spectrum ----------------
__global__ void __launch_bounds__(512, 3) kf_kernel() {
    extern __shared__ float2 S[];
    int d = blockIdx.x;
    int tid = threadIdx.x;
    const float2* krow = (const float2*)(g_kT + (size_t)d * SEQ_LEN);
    fwd_pass1_fused(S, tid, krow);
    __syncthreads();
    fwd_group3<3>(S, tid); __syncthreads();
    fwd_group3<6>(S, tid); __syncthreads();
    fwd_group16(S, tid);   __syncthreads();

    const float invM = 1.0f / 16384.0f;
    float2* Kf = g_Kf + (size_t)d * (NFFT + 1);
    if (tid == 0) {
        float2 c0 = S[PHYS(0)];
        Kf[0]    = make_float2((c0.x + c0.y) * invM, 0.f);
        Kf[NFFT] = make_float2((c0.x - c0.y) * invM, 0.f);
    }
    for (int t = tid; t < 4096; t += 512) {
        int k  = t + 1;
        int p1 = __brev(k) >> 19;
        int p2 = __brev(8192 - k) >> 19;
        float2 C1 = S[PHYS(p1)], C2 = S[PHYS(p2)];
        float Ex = 0.5f * (C1.x + C2.x), Ey = 0.5f * (C1.y - C2.y);
        float Dx = C1.x - C2.x,          Dy = C1.y + C2.y;
        float Ox = 0.5f * Dy,            Oy = -0.5f * Dx;
        float2 w = g_tw[k];
        float wOx = Ox * w.x - Oy * w.y, wOy = Ox * w.y + Oy * w.x;
        Kf[k]        = make_float2((Ex + wOx) * invM, (Ey + wOy) * invM);
        Kf[8192 - k] = make_float2((Ex - wOx) * invM, -(Ey - wOy) * invM);
    }
}

// ---------------- fused conv ----------------
__global__ void __launch_bounds__(512, 3) conv_kernel(const float* __restrict__ bias) {
    extern __shared__ float2 S[];
    int col = blockIdx.x;           // b*768 + d
    int d   = col % HIDDEN;
    int tid = threadIdx.x;

    const float2* row = (const float2*)(g_xT + (size_t)col * SEQ_LEN);
    fwd_pass1_fused(S, tid, row);
    __syncthreads();
    fwd_group3<3>(S, tid); __syncthreads();
    fwd_group3<6>(S, tid); __syncthreads();
    fwd_group16(S, tid);   __syncthreads();

    const float2* Kf = g_Kf + (size_t)d * (NFFT + 1);
    if (tid == 0) {
        float2 c0 = S[PHYS(0)];
        float U0 = c0.x + c0.y, UN = c0.x - c0.y;
        float2 F0 = Kf[0], FN = Kf[NFFT];
        float2 Y0 = make_float2(U0 * F0.x, U0 * F0.y);
        float2 YN = make_float2(UN * FN.x, UN * FN.y);
        float Eyx = 0.5f * (Y0.x + YN.x), Eyy = 0.5f * (Y0.y + YN.y);
        float Dyx = 0.5f * (Y0.x - YN.x), Dyy = 0.5f * (Y0.y - YN.y);
        S[PHYS(0)] = make_float2(Eyx - Dyy, Eyy + Dyx);
    }
    for (int t = tid; t < 4096; t += 512) {
        int k  = t + 1;
        int k2 = 8192 - k;
        int p1 = __brev(k)  >> 19;
        int p2 = __brev(k2) >> 19;
        int q1 = PHYS(p1), q2 = PHYS(p2);
        float2 C1 = S[q1], C2 = S[q2];
        float Ex = 0.5f * (C1.x + C2.x), Ey = 0.5f * (C1.y - C2.y);
        float Dx = C1.x - C2.x,          Dy = C1.y + C2.y;
        float Ox = 0.5f * Dy,            Oy = -0.5f * Dx;
        float2 w = g_tw[k];
        float wOx = Ox * w.x - Oy * w.y, wOy = Ox * w.y + Oy * w.x;
        float2 Uk  = make_float2(Ex + wOx, Ey + wOy);
        float2 UkN = make_float2(Ex - wOx, Ey - wOy);
        float2 F1 = Kf[k];
        float2 F2 = Kf[k2];
        float2 Y1 = cmul(Uk, F1);
        float2 Y2 = cmul(UkN, make_float2(F2.x, -F2.y));
        float2 Eyc = make_float2(0.5f * (Y1.x + Y2.x), 0.5f * (Y1.y + Y2.y));
        float2 Dyc = make_float2(0.5f * (Y1.x - Y2.x), 0.5f * (Y1.y - Y2.y));
        float2 Oyc = make_float2(Dyc.x * w.x + Dyc.y * w.y, Dyc.y * w.x - Dyc.x * w.y);
        float2 Zk  = make_float2(Eyc.x - Oyc.y, Eyc.y + Oyc.x);
        // mirror bin: w2 = g_tw[8192-k] = (-w.x, w.y)
        float2 Y1p = cmul(make_float2(UkN.x, -UkN.y), F2);
        float2 Y2p = cmul(make_float2(Uk.x, -Uk.y), make_float2(F1.x, -F1.y));
        float2 w2  = make_float2(-w.x, w.y);
        float2 Eyp = make_float2(0.5f * (Y1p.x + Y2p.x), 0.5f * (Y1p.y + Y2p.y));
        float2 Dyp = make_float2(0.5f * (Y1p.x - Y2p.x), 0.5f * (Y1p.y - Y2p.y));
        float2 Oyp = make_float2(Dyp.x * w2.x + Dyp.y * w2.y, Dyp.y * w2.x - Dyp.x * w2.y);
        float2 Zk2 = make_float2(Eyp.x - Oyp.y, Eyp.y + Oyp.x);
        S[q1] = Zk;
        S[q2] = Zk2;
    }
    __syncthreads();

    inv_group16(S, tid);   __syncthreads();
    inv_group3<4>(S, tid); __syncthreads();
    inv_group3<7>(S, tid); __syncthreads();

    const float invN = 1.0f / 8192.0f;
    float bv = bias[d];
    float2* orow = (float2*)(g_yT + (size_t)col * SEQ_LEN);
    inv_pass4_fused(S, tid, orow, invN, bv);
}

// ---------------- launch ----------------
extern "C" void kernel_launch(void* const* d_in, const int* in_sizes, int n_in,
                              void* d_out, int out_size) {
    const float* x       = (const float*)d_in[0];
    const float* w_in    = (const float*)d_in[1];
    const float* b_in    = (const float*)d_in[2];
    const float* freq_in = (const float*)d_in[3];
    const float* w_h0    = (const float*)d_in[4];
    const float* b_h0    = (const float*)d_in[5];
    const float* freq_h0 = (const float*)d_in[6];
    const float* w_h1    = (const float*)d_in[7];
    const float* b_h1    = (const float*)d_in[8];
    const float* freq_h1 = (const float*)d_in[9];
    const float* w_out   = (const float*)d_in[10];
    const float* bias    = (const float*)d_in[11];
    float* out = (float*)d_out;

    cudaFuncSetAttribute(kf_kernel,   cudaFuncAttributeMaxDynamicSharedMemorySize, SMEM_BYTES);
    cudaFuncSetAttribute(conv_kernel, cudaFuncAttributeMaxDynamicSharedMemorySize, SMEM_BYTES);

    twiddle_init<<<16, 512>>>();
    filter_kernel<<<SEQ_LEN / 16, 256>>>(w_in, b_in, freq_in, w_h0, b_h0, freq_h0,
                                         w_h1, b_h1, freq_h1, w_out);
    dim3 tblk(32, 8);
    dim3 tgrid(SEQ_LEN / 128, HIDDEN / 32, BATCH);
    transpose_in<<<tgrid, tblk>>>(x);
    dim3 kgrid(SEQ_LEN / 128, HIDDEN / 32, 1);
    transpose_k<<<kgrid, tblk>>>();
    kf_kernel<<<HIDDEN, 512, SMEM_BYTES>>>();
    conv_kernel<<<BATCH * HIDDEN, 512, SMEM_BYTES>>>(bias);
    transpose_out<<<tgrid, tblk>>>(out);
}